// round 1
// baseline (speedup 1.0000x reference)
#include <cuda_runtime.h>
#include <math.h>

#define NS 19200   // T*H*W
#define TT 12
#define HH 40
#define WW 40
#define CC 128

// Scratch (device globals: allocation-free per harness rules)
__device__ float g_xn[NS * CC];        //  9.8 MB  normalized x (flat, original layout)
__device__ float g_qkv[NS * 3 * CC];   // 29.5 MB  qkv rows [p][384]
__device__ float g_att[NS * CC];       //  9.8 MB  attention output rows [p][128]

// ---------------------------------------------------------------------------
// Kernel 1: channel RMS norm in (C,T,H,W) layout.
// xn[c*NS+s] = x[c*NS+s] / max(||x[:,s]||,1e-12) * sqrt(C) * gamma[c]
// ---------------------------------------------------------------------------
__global__ void norm_kernel(const float* __restrict__ x,
                            const float* __restrict__ gamma) {
    int s = blockIdx.x * blockDim.x + threadIdx.x;
    if (s >= NS) return;
    float ss = 0.f;
#pragma unroll 8
    for (int c = 0; c < CC; c++) {
        float v = x[c * NS + s];
        ss = fmaf(v, v, ss);
    }
    float inv = 11.313708498984761f / fmaxf(sqrtf(ss), 1e-12f);  // sqrt(128)/||x||
#pragma unroll 8
    for (int c = 0; c < CC; c++) {
        g_xn[c * NS + s] = x[c * NS + s] * inv * __ldg(&gamma[c]);
    }
}

// ---------------------------------------------------------------------------
// Kernel 2/4: C[M,NN] = A[M,128] @ B[NN,128]^T + bias (+ resid), M=19200.
// MODE 0: A = g_xn (flat-reinterpreted as [19200][128]), Cout = g_qkv, no resid
// MODE 1: A = g_att, Cout = outArg, resid = x (flat residual add)
// 64x64 block tile, 256 threads, 4x4 per thread, BK=32, smem transposed.
// ---------------------------------------------------------------------------
template <int NN, int MODE>
__global__ void __launch_bounds__(256, 2)
gemm_nt(const float* __restrict__ B, const float* __restrict__ bias,
        const float* __restrict__ resid, float* __restrict__ outArg) {
    const int BM = 64, BN = 64, BK = 32;
    __shared__ float As[BK][BM + 4];
    __shared__ float Bs[BK][BN + 4];

    const float* __restrict__ A = (MODE == 0) ? g_xn : g_att;
    float* __restrict__ Cout    = (MODE == 0) ? g_qkv : outArg;

    int tid = threadIdx.x;
    int tx = tid & 15;       // 16 col-groups
    int ty = tid >> 4;       // 16 row-groups
    int bx = blockIdx.x;     // N tile
    int by = blockIdx.y;     // M tile

    float acc[4][4] = {};

    for (int k0 = 0; k0 < CC; k0 += BK) {
        // Load A tile (64 rows x 32 k), transpose into As[k][row]
#pragma unroll
        for (int i = tid; i < BM * BK / 4; i += 256) {
            int r = i >> 3;
            int c4 = (i & 7) << 2;
            float4 v = *(const float4*)(A + (size_t)(by * BM + r) * CC + k0 + c4);
            As[c4 + 0][r] = v.x; As[c4 + 1][r] = v.y;
            As[c4 + 2][r] = v.z; As[c4 + 3][r] = v.w;
        }
        // Load B tile (64 N-rows x 32 k), transpose into Bs[k][col]
#pragma unroll
        for (int i = tid; i < BN * BK / 4; i += 256) {
            int r = i >> 3;
            int c4 = (i & 7) << 2;
            float4 v = *(const float4*)(B + (size_t)(bx * BN + r) * CC + k0 + c4);
            Bs[c4 + 0][r] = v.x; Bs[c4 + 1][r] = v.y;
            Bs[c4 + 2][r] = v.z; Bs[c4 + 3][r] = v.w;
        }
        __syncthreads();
#pragma unroll
        for (int k = 0; k < BK; k++) {
            float4 a4 = *(const float4*)&As[k][ty * 4];
            float4 b4 = *(const float4*)&Bs[k][tx * 4];
            float av[4] = {a4.x, a4.y, a4.z, a4.w};
            float bv[4] = {b4.x, b4.y, b4.z, b4.w};
#pragma unroll
            for (int i = 0; i < 4; i++)
#pragma unroll
                for (int j = 0; j < 4; j++)
                    acc[i][j] = fmaf(av[i], bv[j], acc[i][j]);
        }
        __syncthreads();
    }

    int col = bx * BN + tx * 4;
    float4 b4 = *(const float4*)(bias + col);
    float bb[4] = {b4.x, b4.y, b4.z, b4.w};
#pragma unroll
    for (int i = 0; i < 4; i++) {
        int row = by * BM + ty * 4 + i;
        float4 o;
        o.x = acc[i][0] + bb[0];
        o.y = acc[i][1] + bb[1];
        o.z = acc[i][2] + bb[2];
        o.w = acc[i][3] + bb[3];
        if (MODE == 1) {
            float4 r4 = *(const float4*)(resid + (size_t)row * NN + col);
            o.x += r4.x; o.y += r4.y; o.z += r4.z; o.w += r4.w;
        }
        *(float4*)(Cout + (size_t)row * NN + col) = o;
    }
}

// ---------------------------------------------------------------------------
// Kernel 3: 3x3x3 neighborhood attention. One block (128 thr) per position.
// scores = (q * C^-0.5) . k_n + rpb ; softmax over 27 ; out = sum a_n * v_n
// ---------------------------------------------------------------------------
__global__ void attn_kernel(const float* __restrict__ rpb) {
    __shared__ float qs[128];
    __shared__ float sc[32];   // bias, then bias+score
    __shared__ int   np[32];   // neighbor flat positions

    int p = blockIdx.x;
    int t = p / (HH * WW);
    int rem = p % (HH * WW);
    int h = rem / WW;
    int w = rem % WW;
    int tid = threadIdx.x;

    if (tid < 27) {
        int dt = tid / 9, dh = (tid / 3) % 3, dw = tid % 3;
        int st = min(max(t - 1, 0), TT - 3);
        int sh = min(max(h - 1, 0), HH - 3);
        int sw = min(max(w - 1, 0), WW - 3);
        int nt = st + dt, nh = sh + dh, nw = sw + dw;
        np[tid] = (nt * HH + nh) * WW + nw;
        int bt = nt - t + 2, bh = nh - h + 2, bw = nw - w + 2;
        sc[tid] = __ldg(&rpb[(bt * 5 + bh) * 5 + bw]);
    }
    qs[tid] = g_qkv[(size_t)p * 384 + tid] * 0.08838834764831845f;  // C^-0.5
    __syncthreads();

    int wid = tid >> 5, lane = tid & 31;
    float q0 = qs[lane], q1 = qs[lane + 32], q2 = qs[lane + 64], q3 = qs[lane + 96];

    for (int n = wid; n < 27; n += 4) {
        const float* kr = &g_qkv[(size_t)np[n] * 384 + 128];
        float d = q0 * kr[lane] + q1 * kr[lane + 32] + q2 * kr[lane + 64] + q3 * kr[lane + 96];
#pragma unroll
        for (int o = 16; o; o >>= 1) d += __shfl_xor_sync(0xffffffffu, d, o);
        if (lane == 0) sc[n] += d;
    }
    __syncthreads();

    // softmax weights in registers (redundant across threads; 27 exps each)
    float m = -1e30f;
#pragma unroll
    for (int n = 0; n < 27; n++) m = fmaxf(m, sc[n]);
    float aw[27];
    float den = 0.f;
#pragma unroll
    for (int n = 0; n < 27; n++) {
        aw[n] = __expf(sc[n] - m);
        den += aw[n];
    }
    float invd = 1.0f / den;

    float acc = 0.f;
#pragma unroll
    for (int n = 0; n < 27; n++) {
        acc = fmaf(aw[n], g_qkv[(size_t)np[n] * 384 + 256 + tid], acc);
    }
    g_att[(size_t)p * 128 + tid] = acc * invd;
}

// ---------------------------------------------------------------------------
extern "C" void kernel_launch(void* const* d_in, const int* in_sizes, int n_in,
                              void* d_out, int out_size) {
    const float* x      = (const float*)d_in[0];
    const float* gamma  = (const float*)d_in[1];
    const float* qkv_w  = (const float*)d_in[2];
    const float* qkv_b  = (const float*)d_in[3];
    const float* rpb    = (const float*)d_in[4];
    const float* proj_w = (const float*)d_in[5];
    const float* proj_b = (const float*)d_in[6];
    float* out = (float*)d_out;

    norm_kernel<<<(NS + 255) / 256, 256>>>(x, gamma);
    gemm_nt<384, 0><<<dim3(384 / 64, NS / 64), 256>>>(qkv_w, qkv_b, nullptr, nullptr);
    attn_kernel<<<NS, 128>>>(rpb);
    gemm_nt<128, 1><<<dim3(128 / 64, NS / 64), 256>>>(proj_w, proj_b, x, out);
}

// round 2
// speedup vs baseline: 1.3078x; 1.3078x over previous
#include <cuda_runtime.h>
#include <math.h>
#include <stdint.h>

#define NS 19200   // T*H*W
#define TT 12
#define HH 40
#define WW 40
#define CC 128

// Scratch (device globals: allocation-free per harness rules)
__device__ float g_xn[NS * CC];        //  normalized x (flat, original layout)
__device__ float g_qkv[NS * 3 * CC];   //  qkv rows [p][384]
__device__ float g_att[NS * CC];       //  attention output rows [p][128]

__device__ __forceinline__ uint32_t f2tf32(float f) {
    uint32_t u;
    asm("cvt.rna.tf32.f32 %0, %1;" : "=r"(u) : "f"(f));
    return u;
}

__device__ __forceinline__ void mma_tf32(float* c, const uint32_t* a, const uint32_t* b) {
    asm volatile(
        "mma.sync.aligned.m16n8k8.row.col.f32.tf32.tf32.f32 "
        "{%0,%1,%2,%3}, {%4,%5,%6,%7}, {%8,%9}, {%0,%1,%2,%3};\n"
        : "+f"(c[0]), "+f"(c[1]), "+f"(c[2]), "+f"(c[3])
        : "r"(a[0]), "r"(a[1]), "r"(a[2]), "r"(a[3]), "r"(b[0]), "r"(b[1]));
}

// ---------------------------------------------------------------------------
// Kernel 1: channel RMS norm in (C,T,H,W) layout.
// ---------------------------------------------------------------------------
__global__ void norm_kernel(const float* __restrict__ x,
                            const float* __restrict__ gamma) {
    int s = blockIdx.x * blockDim.x + threadIdx.x;
    if (s >= NS) return;
    float ss = 0.f;
#pragma unroll 8
    for (int c = 0; c < CC; c++) {
        float v = x[c * NS + s];
        ss = fmaf(v, v, ss);
    }
    float inv = 11.313708498984761f / fmaxf(sqrtf(ss), 1e-12f);  // sqrt(128)/||x||
#pragma unroll 8
    for (int c = 0; c < CC; c++) {
        g_xn[c * NS + s] = x[c * NS + s] * inv * __ldg(&gamma[c]);
    }
}

// ---------------------------------------------------------------------------
// Kernel 2/4: tf32 tensor-core GEMM. C[M,NN] = A[M,128] @ B[NN,128]^T + bias
// (+resid for MODE 1). Block tile 128x128, BK=32, 256 threads (8 warps 2x4,
// warp tile 64x32, 16 mma m16n8k8 per k-step).
// ---------------------------------------------------------------------------
#define LDT 136   // smem row stride (floats); 136%32=8 -> conflict-free frag LDS

template <int NN, int MODE>
__global__ void __launch_bounds__(256, 2)
gemm_tf32(const float* __restrict__ Bw, const float* __restrict__ bias,
          const float* __restrict__ resid, float* __restrict__ outArg) {
    __shared__ uint32_t As[32 * LDT];  // [k][m]
    __shared__ uint32_t Bs[32 * LDT];  // [k][n]

    const float* __restrict__ A = (MODE == 0) ? g_xn : g_att;
    float* __restrict__ Cout    = (MODE == 0) ? g_qkv : outArg;

    int tid = threadIdx.x;
    int lane = tid & 31;
    int warp = tid >> 5;
    int wm = warp & 1;    // 2 warps in M -> 64 rows each
    int wn = warp >> 1;   // 4 warps in N -> 32 cols each
    int g = lane >> 2, tg = lane & 3;

    float acc[4][4][4];
#pragma unroll
    for (int i = 0; i < 4; i++)
#pragma unroll
        for (int j = 0; j < 4; j++)
#pragma unroll
            for (int e = 0; e < 4; e++) acc[i][j][e] = 0.f;

    int r = tid >> 1;            // 0..127
    int c0 = (tid & 1) * 16;     // 0 or 16
    const float* Ag = A  + (size_t)(blockIdx.y * 128 + r) * CC + c0;
    const float* Bg = Bw + (size_t)(blockIdx.x * 128 + r) * CC + c0;

#pragma unroll
    for (int k0 = 0; k0 < 128; k0 += 32) {
#pragma unroll
        for (int j = 0; j < 4; j++) {
            float4 va = *(const float4*)(Ag + k0 + j * 4);
            float4 vb = *(const float4*)(Bg + k0 + j * 4);
            int kk = c0 + j * 4;
            As[(kk + 0) * LDT + r] = f2tf32(va.x);
            As[(kk + 1) * LDT + r] = f2tf32(va.y);
            As[(kk + 2) * LDT + r] = f2tf32(va.z);
            As[(kk + 3) * LDT + r] = f2tf32(va.w);
            Bs[(kk + 0) * LDT + r] = f2tf32(vb.x);
            Bs[(kk + 1) * LDT + r] = f2tf32(vb.y);
            Bs[(kk + 2) * LDT + r] = f2tf32(vb.z);
            Bs[(kk + 3) * LDT + r] = f2tf32(vb.w);
        }
        __syncthreads();
#pragma unroll
        for (int ks = 0; ks < 4; ks++) {
            int kb = ks * 8;
            uint32_t af[4][4], bf[4][2];
#pragma unroll
            for (int mt = 0; mt < 4; mt++) {
                int m = wm * 64 + mt * 16 + g;
                af[mt][0] = As[(kb + tg    ) * LDT + m];
                af[mt][1] = As[(kb + tg    ) * LDT + m + 8];
                af[mt][2] = As[(kb + tg + 4) * LDT + m];
                af[mt][3] = As[(kb + tg + 4) * LDT + m + 8];
            }
#pragma unroll
            for (int nt = 0; nt < 4; nt++) {
                int n = wn * 32 + nt * 8 + g;
                bf[nt][0] = Bs[(kb + tg    ) * LDT + n];
                bf[nt][1] = Bs[(kb + tg + 4) * LDT + n];
            }
#pragma unroll
            for (int mt = 0; mt < 4; mt++)
#pragma unroll
                for (int nt = 0; nt < 4; nt++)
                    mma_tf32(acc[mt][nt], af[mt], bf[nt]);
        }
        __syncthreads();
    }

    // Epilogue: c0,c1 -> (row g, cols 2tg,2tg+1); c2,c3 -> row g+8
#pragma unroll
    for (int nt = 0; nt < 4; nt++) {
        int n = blockIdx.x * 128 + wn * 32 + nt * 8 + 2 * tg;
        float2 bb = *(const float2*)(bias + n);
#pragma unroll
        for (int mt = 0; mt < 4; mt++) {
            int row0 = blockIdx.y * 128 + wm * 64 + mt * 16 + g;
            float2 o0 = { acc[mt][nt][0] + bb.x, acc[mt][nt][1] + bb.y };
            float2 o1 = { acc[mt][nt][2] + bb.x, acc[mt][nt][3] + bb.y };
            if (MODE == 1) {
                float2 r0 = *(const float2*)(resid + (size_t)row0 * NN + n);
                float2 r1 = *(const float2*)(resid + (size_t)(row0 + 8) * NN + n);
                o0.x += r0.x; o0.y += r0.y;
                o1.x += r1.x; o1.y += r1.y;
            }
            *(float2*)(Cout + (size_t)row0 * NN + n) = o0;
            *(float2*)(Cout + (size_t)(row0 + 8) * NN + n) = o1;
        }
    }
}

// ---------------------------------------------------------------------------
// Kernel 3: 3x3x3 neighborhood attention, tiled. One CTA (256 thr, 8 warps)
// handles 8 positions (1t x 2h x 4w). Union neighborhood = 3x4x6 = 72 k/v
// rows staged in smem once (2x traffic cut vs per-position). Warp j owns
// position j: scores via float4 LDS + butterfly, one exp per score.
// ---------------------------------------------------------------------------
#define KLD 132   // smem row stride for k/v/q rows

__global__ void __launch_bounds__(256)
attn_kernel(const float* __restrict__ rpb) {
    extern __shared__ float sm[];
    float* ksm = sm;                      // 72*KLD
    float* vsm = ksm + 72 * KLD;          // 72*KLD
    float* qsm = vsm + 72 * KLD;          // 8*KLD
    float* sc  = qsm + 8 * KLD;           // 8*32
    float* aw  = sc + 256;                // 8*32
    int*   sl  = (int*)(aw + 256);        // 8*32

    int tid = threadIdx.x, lane = tid & 31, warp = tid >> 5;
    int w0 = blockIdx.x * 4, h0 = blockIdx.y * 2, t = blockIdx.z;

    int st  = min(max(t  - 1, 0), TT - 3);   // t window start (3 rows)
    int hlo = min(max(h0 - 1, 0), HH - 3);   // h union start (<=4 rows)
    int wlo = min(max(w0 - 1, 0), WW - 3);   // w union start (<=6 cols)

    // warp j -> position (t, h0 + j>>2, w0 + (j&3))
    int ph = h0 + (warp >> 2), pw = w0 + (warp & 3);
    int p  = (t * HH + ph) * WW + pw;

    // per-position rpb bias + smem slot for each of 27 neighbors
    if (lane < 27) {
        int dt = lane / 9, dh = (lane / 3) % 3, dw = lane % 3;
        int sh = min(max(ph - 1, 0), HH - 3);
        int sw = min(max(pw - 1, 0), WW - 3);
        int nt = st + dt, nh = sh + dh, nw = sw + dw;
        sl[warp * 32 + lane] = (dt * 4 + (nh - hlo)) * 6 + (nw - wlo);
        int bt = nt - t + 2, bh = nh - ph + 2, bw = nw - pw + 2;
        sc[warp * 32 + lane] = __ldg(&rpb[(bt * 5 + bh) * 5 + bw]);
    }

    // q (scaled by C^-0.5)
    {
        float4 q4 = *(const float4*)(g_qkv + (size_t)p * 384 + lane * 4);
        const float s = 0.08838834764831845f;
        q4.x *= s; q4.y *= s; q4.z *= s; q4.w *= s;
        *(float4*)(qsm + warp * KLD + lane * 4) = q4;
    }

    // stage union k/v rows (clamped duplicates at borders are never indexed)
    for (int rowid = warp; rowid < 72; rowid += 8) {
        int dt = rowid / 24, rrem = rowid % 24;
        int dh = rrem / 6, dw = rrem % 6;
        int nh = min(hlo + dh, HH - 1);
        int nw = min(wlo + dw, WW - 1);
        int np = ((st + dt) * HH + nh) * WW + nw;
        const float* base = g_qkv + (size_t)np * 384;
        *(float4*)(ksm + rowid * KLD + lane * 4) = *(const float4*)(base + 128 + lane * 4);
        *(float4*)(vsm + rowid * KLD + lane * 4) = *(const float4*)(base + 256 + lane * 4);
    }
    __syncthreads();

    // scores: 27 dot-128 per warp
    {
        float4 q4 = *(const float4*)(qsm + warp * KLD + lane * 4);
#pragma unroll
        for (int n = 0; n < 27; n++) {
            int slot = sl[warp * 32 + n];
            float4 k4 = *(const float4*)(ksm + slot * KLD + lane * 4);
            float d = q4.x * k4.x + q4.y * k4.y + q4.z * k4.z + q4.w * k4.w;
#pragma unroll
            for (int o = 16; o; o >>= 1) d += __shfl_xor_sync(0xffffffffu, d, o);
            if (lane == 0) sc[warp * 32 + n] += d;
        }
    }
    __syncwarp();

    // softmax over 27 (one exp per score per warp)
    {
        float s = (lane < 27) ? sc[warp * 32 + lane] : -1e30f;
        float m = s;
#pragma unroll
        for (int o = 16; o; o >>= 1) m = fmaxf(m, __shfl_xor_sync(0xffffffffu, m, o));
        float e = (lane < 27) ? __expf(s - m) : 0.f;
        float den = e;
#pragma unroll
        for (int o = 16; o; o >>= 1) den += __shfl_xor_sync(0xffffffffu, den, o);
        aw[warp * 32 + lane] = e / den;
    }
    __syncwarp();

    // out = sum_n a_n * v_n
    {
        float4 acc = {0.f, 0.f, 0.f, 0.f};
#pragma unroll
        for (int n = 0; n < 27; n++) {
            float a = aw[warp * 32 + n];
            int slot = sl[warp * 32 + n];
            float4 v4 = *(const float4*)(vsm + slot * KLD + lane * 4);
            acc.x = fmaf(a, v4.x, acc.x);
            acc.y = fmaf(a, v4.y, acc.y);
            acc.z = fmaf(a, v4.z, acc.z);
            acc.w = fmaf(a, v4.w, acc.w);
        }
        *(float4*)(g_att + (size_t)p * 128 + lane * 4) = acc;
    }
}

static const int ATTN_SMEM = (72 * KLD * 2 + 8 * KLD + 256 + 256 + 256) * 4;  // 83328 B

// ---------------------------------------------------------------------------
extern "C" void kernel_launch(void* const* d_in, const int* in_sizes, int n_in,
                              void* d_out, int out_size) {
    const float* x      = (const float*)d_in[0];
    const float* gamma  = (const float*)d_in[1];
    const float* qkv_w  = (const float*)d_in[2];
    const float* qkv_b  = (const float*)d_in[3];
    const float* rpb    = (const float*)d_in[4];
    const float* proj_w = (const float*)d_in[5];
    const float* proj_b = (const float*)d_in[6];
    float* out = (float*)d_out;

    cudaFuncSetAttribute(attn_kernel, cudaFuncAttributeMaxDynamicSharedMemorySize, ATTN_SMEM);

    norm_kernel<<<(NS + 255) / 256, 256>>>(x, gamma);
    gemm_tf32<384, 0><<<dim3(3, NS / 128), 256>>>(qkv_w, qkv_b, nullptr, nullptr);
    attn_kernel<<<dim3(WW / 4, HH / 2, TT), 256, ATTN_SMEM>>>(rpb);
    gemm_tf32<128, 1><<<dim3(1, NS / 128), 256>>>(proj_w, proj_b, x, out);
}